// round 1
// baseline (speedup 1.0000x reference)
#include <cuda_runtime.h>
#include <cuda_bf16.h>

// SpatialAttention, factored: m1@m2 = Qt(K Jt)K  ->  rank-8 bilinear form.
// B=2, W=D=H=16 -> N=4096, C=32. All fp32.

#define BATCH 2
#define NSP   4096          // W*D*H
#define NC    32
#define MSPLIT 8
#define MT    64            // m-tile in smem
#define TILE_N 128

// ---- scratch (__device__ globals: allocation-free) ----
__device__ float g_Q[BATCH * NSP * 8];     // [b][n*8+oc] == Qm[c][n] reinterpreted
__device__ float g_K[BATCH * NSP * 8];
__device__ float g_J[BATCH * NSP * 8];
__device__ float g_V[BATCH * NSP * NC];    // [b][n*32+c]
__device__ float g_M[BATCH * 64];          // [b][a*8+j]
__device__ float g_R[BATCH * NSP * 8];     // [b][n*8+j]
__device__ float g_P[MSPLIT * BATCH * NSP * NC]; // partial sums

#define XIDX(b,w,d,h,c) (((((((b)*16+(w))*16+(d))*16)+(h))*32)+(c))

// ============================================================
// 1) Projections: Q (conv over D, k=3), K (over W), J (over H), V (1x1x1).
//    One block per (b,w,d) line of 16 h positions; 128 threads = 16 h x 8 oc.
// ============================================================
__global__ __launch_bounds__(128) void proj_kernel(
    const float* __restrict__ x,
    const float* __restrict__ qw, const float* __restrict__ qb,
    const float* __restrict__ qs, const float* __restrict__ qo,
    const float* __restrict__ kw, const float* __restrict__ kb,
    const float* __restrict__ ks, const float* __restrict__ ko,
    const float* __restrict__ jw, const float* __restrict__ jb,
    const float* __restrict__ js, const float* __restrict__ jo,
    const float* __restrict__ vw, const float* __restrict__ vb,
    const float* __restrict__ vs, const float* __restrict__ vo)
{
    int d = blockIdx.x, w = blockIdx.y, b = blockIdx.z;
    int tid = threadIdx.x;

    __shared__ float s_c[18][33];                 // center line, h padded
    __shared__ float s_dm[16][33], s_dp[16][33];  // d-1, d+1
    __shared__ float s_wm[16][33], s_wp[16][33];  // w-1, w+1
    __shared__ float s_qw[3][32][8], s_kw[3][32][8], s_jw[3][32][8];
    __shared__ float s_vw[32][32];

    // weights (layouts match global row-major (t,ci,oc) / (ci,oc))
    for (int i = tid; i < 768; i += 128) {
        (&s_qw[0][0][0])[i] = qw[i];
        (&s_kw[0][0][0])[i] = kw[i];
        (&s_jw[0][0][0])[i] = jw[i];
    }
    for (int i = tid; i < 1024; i += 128) (&s_vw[0][0])[i] = vw[i];

    // x lines
    for (int i = tid; i < 512; i += 128) {
        int h = i >> 5, c = i & 31;
        s_c [h + 1][c] = x[XIDX(b, w, d, h, c)];
        s_dm[h][c] = (d > 0)  ? x[XIDX(b, w, d - 1, h, c)] : 0.f;
        s_dp[h][c] = (d < 15) ? x[XIDX(b, w, d + 1, h, c)] : 0.f;
        s_wm[h][c] = (w > 0)  ? x[XIDX(b, w - 1, d, h, c)] : 0.f;
        s_wp[h][c] = (w < 15) ? x[XIDX(b, w + 1, d, h, c)] : 0.f;
    }
    if (tid < 32)              s_c[0][tid]       = 0.f;
    else if (tid < 64)         s_c[17][tid - 32] = 0.f;
    __syncthreads();

    int h = tid >> 3, oc = tid & 7;
    float q = 0.f, k = 0.f, j = 0.f;
    float v0 = 0.f, v1 = 0.f, v2 = 0.f, v3 = 0.f;
    #pragma unroll
    for (int ci = 0; ci < 32; ci++) {
        float xc  = s_c [h + 1][ci];
        float xdm = s_dm[h][ci], xdp = s_dp[h][ci];
        float xwm = s_wm[h][ci], xwp = s_wp[h][ci];
        float xhm = s_c [h][ci], xhp = s_c [h + 2][ci];
        q += xdm * s_qw[0][ci][oc] + xc * s_qw[1][ci][oc] + xdp * s_qw[2][ci][oc];
        k += xwm * s_kw[0][ci][oc] + xc * s_kw[1][ci][oc] + xwp * s_kw[2][ci][oc];
        j += xhm * s_jw[0][ci][oc] + xc * s_jw[1][ci][oc] + xhp * s_jw[2][ci][oc];
        v0 += xc * s_vw[ci][oc];
        v1 += xc * s_vw[ci][oc + 8];
        v2 += xc * s_vw[ci][oc + 16];
        v3 += xc * s_vw[ci][oc + 24];
    }

    int n = w * 256 + d * 16 + h;
    g_Q[b * (NSP * 8) + n * 8 + oc] = fmaxf((q + qb[oc]) * qs[oc] + qo[oc], 0.f);
    g_K[b * (NSP * 8) + n * 8 + oc] = fmaxf((k + kb[oc]) * ks[oc] + ko[oc], 0.f);
    g_J[b * (NSP * 8) + n * 8 + oc] = fmaxf((j + jb[oc]) * js[oc] + jo[oc], 0.f);
    float vv[4] = {v0, v1, v2, v3};
    #pragma unroll
    for (int p = 0; p < 4; p++) {
        int co = oc + 8 * p;
        g_V[b * (NSP * NC) + n * NC + co] =
            fmaxf((vv[p] + vb[co]) * vs[co] + vo[co], 0.f);
    }
}

// ============================================================
// 2) M[b][a][j] = sum_n Km[a][n] * Jm[j][n]   (8x8 per batch)
// ============================================================
__global__ __launch_bounds__(256) void m_kernel()
{
    int a = blockIdx.x, j = blockIdx.y, b = blockIdx.z;
    const float* K = g_K + b * (NSP * 8) + a * NSP;
    const float* J = g_J + b * (NSP * 8) + j * NSP;
    float p = 0.f;
    for (int n = threadIdx.x; n < NSP; n += 256) p += K[n] * J[n];
    __shared__ float red[256];
    red[threadIdx.x] = p;
    __syncthreads();
    for (int s = 128; s > 0; s >>= 1) {
        if (threadIdx.x < s) red[threadIdx.x] += red[threadIdx.x + s];
        __syncthreads();
    }
    if (threadIdx.x == 0) g_M[b * 64 + a * 8 + j] = red[0];
}

// ============================================================
// 3) R[b][n][j] = sum_a Qm[a][n] * M[a][j]
// ============================================================
__global__ __launch_bounds__(256) void r_kernel()
{
    int g = blockIdx.x * 256 + threadIdx.x;  // 0..8191
    int b = g >> 12, n = g & (NSP - 1);
    float q[8];
    #pragma unroll
    for (int a = 0; a < 8; a++) q[a] = g_Q[b * (NSP * 8) + a * NSP + n];
    #pragma unroll
    for (int j = 0; j < 8; j++) {
        float r = 0.f;
        #pragma unroll
        for (int a = 0; a < 8; a++) r += q[a] * g_M[b * 64 + a * 8 + j];
        g_R[b * (NSP * 8) + n * 8 + j] = r;
    }
}

// ============================================================
// 4) partial[n][c] = sum_{m in split} sigmoid(R[n].K[:,m]) * V[m][c]
//    128 threads = 128 rows; m split 8-way across blocks for occupancy.
// ============================================================
__global__ __launch_bounds__(128) void attn_kernel()
{
    int ms = blockIdx.x;   // 0..MSPLIT-1
    int nt = blockIdx.y;   // 0..31
    int b  = blockIdx.z;
    int tid = threadIdx.x;
    int n = nt * TILE_N + tid;

    const float* Rn = g_R + b * (NSP * 8) + n * 8;
    float4 r0 = *(const float4*)(Rn);
    float4 r1 = *(const float4*)(Rn + 4);

    float acc[NC];
    #pragma unroll
    for (int c = 0; c < NC; c++) acc[c] = 0.f;

    __shared__ float sk[MT][8];
    __shared__ float sv[MT][NC];
    const float* Kb = g_K + b * (NSP * 8);
    const float* Vb = g_V + b * (NSP * NC);

    const int mbeg = ms * (NSP / MSPLIT);
    const int mend = mbeg + (NSP / MSPLIT);
    for (int m0 = mbeg; m0 < mend; m0 += MT) {
        __syncthreads();
        for (int i = tid; i < MT * 8; i += 128) {
            int j = i >> 6, mm = i & (MT - 1);
            sk[mm][j] = Kb[j * NSP + m0 + mm];
        }
        for (int i = tid; i < MT * NC; i += 128)
            (&sv[0][0])[i] = Vb[m0 * NC + i];
        __syncthreads();

        #pragma unroll 4
        for (int mm = 0; mm < MT; mm++) {
            float4 k0 = *(const float4*)&sk[mm][0];
            float4 k1 = *(const float4*)&sk[mm][4];
            float t = r0.x * k0.x + r0.y * k0.y + r0.z * k0.z + r0.w * k0.w
                    + r1.x * k1.x + r1.y * k1.y + r1.z * k1.z + r1.w * k1.w;
            float e = __expf(-t);
            float s = __fdividef(1.f, 1.f + e);
            #pragma unroll
            for (int c4 = 0; c4 < 8; c4++) {
                float4 v = *(const float4*)&sv[mm][c4 * 4];
                acc[c4 * 4 + 0] += s * v.x;
                acc[c4 * 4 + 1] += s * v.y;
                acc[c4 * 4 + 2] += s * v.z;
                acc[c4 * 4 + 3] += s * v.w;
            }
        }
    }

    float* P = g_P + (((size_t)ms * BATCH + b) * NSP + n) * NC;
    #pragma unroll
    for (int c4 = 0; c4 < 8; c4++)
        *(float4*)(P + c4 * 4) = make_float4(acc[c4 * 4], acc[c4 * 4 + 1],
                                             acc[c4 * 4 + 2], acc[c4 * 4 + 3]);
}

// ============================================================
// 5) y = gamma * sum_splits(P) + x   (deterministic reduce)
// ============================================================
__global__ __launch_bounds__(256) void finish_kernel(
    const float* __restrict__ x, const float* __restrict__ gamma,
    float* __restrict__ out)
{
    int i = blockIdx.x * 256 + threadIdx.x;  // 0 .. B*N*C-1
    float g = gamma[0];
    float sum = 0.f;
    #pragma unroll
    for (int s = 0; s < MSPLIT; s++) sum += g_P[(size_t)s * (BATCH * NSP * NC) + i];
    out[i] = g * sum + x[i];
}

// ============================================================
extern "C" void kernel_launch(void* const* d_in, const int* in_sizes, int n_in,
                              void* d_out, int out_size)
{
    const float* x     = (const float*)d_in[0];
    const float* gamma = (const float*)d_in[1];
    const float* qw = (const float*)d_in[2];
    const float* qb = (const float*)d_in[3];
    const float* qs = (const float*)d_in[4];
    const float* qo = (const float*)d_in[5];
    const float* kw = (const float*)d_in[6];
    const float* kb = (const float*)d_in[7];
    const float* ks = (const float*)d_in[8];
    const float* ko = (const float*)d_in[9];
    const float* jw = (const float*)d_in[10];
    const float* jb = (const float*)d_in[11];
    const float* js = (const float*)d_in[12];
    const float* jo = (const float*)d_in[13];
    const float* vw = (const float*)d_in[14];
    const float* vb = (const float*)d_in[15];
    const float* vs = (const float*)d_in[16];
    const float* vo = (const float*)d_in[17];
    float* out = (float*)d_out;

    proj_kernel<<<dim3(16, 16, BATCH), 128>>>(x, qw, qb, qs, qo,
                                              kw, kb, ks, ko,
                                              jw, jb, js, jo,
                                              vw, vb, vs, vo);
    m_kernel<<<dim3(8, 8, BATCH), 256>>>();
    r_kernel<<<(BATCH * NSP) / 256, 256>>>();
    attn_kernel<<<dim3(MSPLIT, NSP / TILE_N, BATCH), 128>>>();
    finish_kernel<<<(BATCH * NSP * NC) / 256, 256>>>(x, gamma, out);
}

// round 2
// speedup vs baseline: 1.1107x; 1.1107x over previous
#include <cuda_runtime.h>
#include <cuda_bf16.h>

// SpatialAttention, factored: m1@m2 = Qt(K Jt)K  ->  rank-8 bilinear form.
// B=2, W=D=H=16 -> N=4096, C=32. All fp32.
// R1: attn kernel does 2 rows/thread + packed fma.rn.f32x2 accumulate.

#define BATCH 2
#define NSP   4096          // W*D*H
#define NC    32
#define MSPLIT 16
#define MT    64            // m-tile in smem
#define TILE_N 256          // rows per block (128 threads x 2 rows)

typedef unsigned long long ull;

// ---- scratch (__device__ globals: allocation-free) ----
__device__ float g_Q[BATCH * NSP * 8];     // stored [n*8+oc], read as reshaped [oc][n]
__device__ float g_K[BATCH * NSP * 8];
__device__ float g_J[BATCH * NSP * 8];
__device__ float g_V[BATCH * NSP * NC];    // [n*32+c]
__device__ float g_M[BATCH * 64];          // [a*8+j]
__device__ float g_R[BATCH * NSP * 8];     // [n*8+j]
__device__ float g_P[MSPLIT * BATCH * NSP * NC]; // partial sums

#define XIDX(b,w,d,h,c) (((((((b)*16+(w))*16+(d))*16)+(h))*32)+(c))

__device__ __forceinline__ void fma2(ull& acc, ull a, ull b) {
    asm("fma.rn.f32x2 %0, %1, %2, %3;" : "=l"(acc) : "l"(a), "l"(b), "l"(acc));
}
__device__ __forceinline__ ull pack2(float lo, float hi) {
    ull r; asm("mov.b64 %0, {%1, %2};" : "=l"(r) : "f"(lo), "f"(hi)); return r;
}
__device__ __forceinline__ float2 unpack2(ull v) {
    float2 r; asm("mov.b64 {%0, %1}, %2;" : "=f"(r.x), "=f"(r.y) : "l"(v)); return r;
}

// ============================================================
// 1) Projections: Q (conv over D, k=3), K (over W), J (over H), V (1x1x1).
// ============================================================
__global__ __launch_bounds__(128) void proj_kernel(
    const float* __restrict__ x,
    const float* __restrict__ qw, const float* __restrict__ qb,
    const float* __restrict__ qs, const float* __restrict__ qo,
    const float* __restrict__ kw, const float* __restrict__ kb,
    const float* __restrict__ ks, const float* __restrict__ ko,
    const float* __restrict__ jw, const float* __restrict__ jb,
    const float* __restrict__ js, const float* __restrict__ jo,
    const float* __restrict__ vw, const float* __restrict__ vb,
    const float* __restrict__ vs, const float* __restrict__ vo)
{
    int d = blockIdx.x, w = blockIdx.y, b = blockIdx.z;
    int tid = threadIdx.x;

    __shared__ float s_c[18][33];                 // center line, h padded
    __shared__ float s_dm[16][33], s_dp[16][33];  // d-1, d+1
    __shared__ float s_wm[16][33], s_wp[16][33];  // w-1, w+1
    __shared__ float s_qw[3][32][8], s_kw[3][32][8], s_jw[3][32][8];
    __shared__ float s_vw[32][32];

    for (int i = tid; i < 768; i += 128) {
        (&s_qw[0][0][0])[i] = qw[i];
        (&s_kw[0][0][0])[i] = kw[i];
        (&s_jw[0][0][0])[i] = jw[i];
    }
    for (int i = tid; i < 1024; i += 128) (&s_vw[0][0])[i] = vw[i];

    for (int i = tid; i < 512; i += 128) {
        int h = i >> 5, c = i & 31;
        s_c [h + 1][c] = x[XIDX(b, w, d, h, c)];
        s_dm[h][c] = (d > 0)  ? x[XIDX(b, w, d - 1, h, c)] : 0.f;
        s_dp[h][c] = (d < 15) ? x[XIDX(b, w, d + 1, h, c)] : 0.f;
        s_wm[h][c] = (w > 0)  ? x[XIDX(b, w - 1, d, h, c)] : 0.f;
        s_wp[h][c] = (w < 15) ? x[XIDX(b, w + 1, d, h, c)] : 0.f;
    }
    if (tid < 32)              s_c[0][tid]       = 0.f;
    else if (tid < 64)         s_c[17][tid - 32] = 0.f;
    __syncthreads();

    int h = tid >> 3, oc = tid & 7;
    float q = 0.f, k = 0.f, j = 0.f;
    float v0 = 0.f, v1 = 0.f, v2 = 0.f, v3 = 0.f;
    #pragma unroll
    for (int ci = 0; ci < 32; ci++) {
        float xc  = s_c [h + 1][ci];
        float xdm = s_dm[h][ci], xdp = s_dp[h][ci];
        float xwm = s_wm[h][ci], xwp = s_wp[h][ci];
        float xhm = s_c [h][ci], xhp = s_c [h + 2][ci];
        q += xdm * s_qw[0][ci][oc] + xc * s_qw[1][ci][oc] + xdp * s_qw[2][ci][oc];
        k += xwm * s_kw[0][ci][oc] + xc * s_kw[1][ci][oc] + xwp * s_kw[2][ci][oc];
        j += xhm * s_jw[0][ci][oc] + xc * s_jw[1][ci][oc] + xhp * s_jw[2][ci][oc];
        v0 += xc * s_vw[ci][oc];
        v1 += xc * s_vw[ci][oc + 8];
        v2 += xc * s_vw[ci][oc + 16];
        v3 += xc * s_vw[ci][oc + 24];
    }

    int n = w * 256 + d * 16 + h;
    g_Q[b * (NSP * 8) + n * 8 + oc] = fmaxf((q + qb[oc]) * qs[oc] + qo[oc], 0.f);
    g_K[b * (NSP * 8) + n * 8 + oc] = fmaxf((k + kb[oc]) * ks[oc] + ko[oc], 0.f);
    g_J[b * (NSP * 8) + n * 8 + oc] = fmaxf((j + jb[oc]) * js[oc] + jo[oc], 0.f);
    float vv[4] = {v0, v1, v2, v3};
    #pragma unroll
    for (int p = 0; p < 4; p++) {
        int co = oc + 8 * p;
        g_V[b * (NSP * NC) + n * NC + co] =
            fmaxf((vv[p] + vb[co]) * vs[co] + vo[co], 0.f);
    }
}

// ============================================================
// 2) M[b][a][j] = sum_n Km[a][n] * Jm[j][n]   (8x8 per batch)
// ============================================================
__global__ __launch_bounds__(256) void m_kernel()
{
    int a = blockIdx.x, j = blockIdx.y, b = blockIdx.z;
    const float* K = g_K + b * (NSP * 8) + a * NSP;
    const float* J = g_J + b * (NSP * 8) + j * NSP;
    float p = 0.f;
    for (int n = threadIdx.x; n < NSP; n += 256) p += K[n] * J[n];
    __shared__ float red[256];
    red[threadIdx.x] = p;
    __syncthreads();
    for (int s = 128; s > 0; s >>= 1) {
        if (threadIdx.x < s) red[threadIdx.x] += red[threadIdx.x + s];
        __syncthreads();
    }
    if (threadIdx.x == 0) g_M[b * 64 + a * 8 + j] = red[0];
}

// ============================================================
// 3) R[b][n][j] = sum_a Qm[a][n] * M[a][j]
// ============================================================
__global__ __launch_bounds__(256) void r_kernel()
{
    int g = blockIdx.x * 256 + threadIdx.x;  // 0..8191
    int b = g >> 12, n = g & (NSP - 1);
    float q[8];
    #pragma unroll
    for (int a = 0; a < 8; a++) q[a] = g_Q[b * (NSP * 8) + a * NSP + n];
    #pragma unroll
    for (int j = 0; j < 8; j++) {
        float r = 0.f;
        #pragma unroll
        for (int a = 0; a < 8; a++) r += q[a] * g_M[b * 64 + a * 8 + j];
        g_R[b * (NSP * 8) + n * 8 + j] = r;
    }
}

// ============================================================
// 4) partial[n][c] = sum_{m in split} sigmoid(R[n].K[:,m]) * V[m][c]
//    2 rows per thread (amortize broadcast smem loads), packed f32x2 accum.
// ============================================================
__global__ __launch_bounds__(128) void attn_kernel()
{
    int ms = blockIdx.x;   // 0..MSPLIT-1
    int nt = blockIdx.y;   // 0..NSP/TILE_N-1
    int b  = blockIdx.z;
    int tid = threadIdx.x;
    int n0 = nt * TILE_N + tid;
    int n1 = n0 + 128;

    const float* Rb = g_R + b * (NSP * 8);
    float4 ra0 = *(const float4*)(Rb + n0 * 8);
    float4 ra1 = *(const float4*)(Rb + n0 * 8 + 4);
    float4 rb0 = *(const float4*)(Rb + n1 * 8);
    float4 rb1 = *(const float4*)(Rb + n1 * 8 + 4);

    ull acc0[16], acc1[16];
    #pragma unroll
    for (int i = 0; i < 16; i++) { acc0[i] = 0ULL; acc1[i] = 0ULL; }

    __shared__ float sk[MT][8];
    __shared__ float sv[MT][NC];
    const float* Kb = g_K + b * (NSP * 8);
    const float* Vb = g_V + b * (NSP * NC);

    const int mbeg = ms * (NSP / MSPLIT);
    const int mend = mbeg + (NSP / MSPLIT);
    for (int m0 = mbeg; m0 < mend; m0 += MT) {
        __syncthreads();
        for (int i = tid; i < MT * 8; i += 128) {
            int j = i >> 6, mm = i & (MT - 1);
            sk[mm][j] = Kb[j * NSP + m0 + mm];
        }
        for (int i = tid; i < MT * NC; i += 128)
            (&sv[0][0])[i] = Vb[m0 * NC + i];
        __syncthreads();

        #pragma unroll 2
        for (int mm = 0; mm < MT; mm++) {
            float4 k0 = *(const float4*)&sk[mm][0];
            float4 k1 = *(const float4*)&sk[mm][4];
            float t0 = ra0.x * k0.x + ra0.y * k0.y + ra0.z * k0.z + ra0.w * k0.w
                     + ra1.x * k1.x + ra1.y * k1.y + ra1.z * k1.z + ra1.w * k1.w;
            float t1 = rb0.x * k0.x + rb0.y * k0.y + rb0.z * k0.z + rb0.w * k0.w
                     + rb1.x * k1.x + rb1.y * k1.y + rb1.z * k1.z + rb1.w * k1.w;
            float s0 = __fdividef(1.f, 1.f + __expf(-t0));
            float s1 = __fdividef(1.f, 1.f + __expf(-t1));
            ull ss0 = pack2(s0, s0);
            ull ss1 = pack2(s1, s1);
            #pragma unroll
            for (int i = 0; i < 8; i++) {
                ulonglong2 v = *(const ulonglong2*)&sv[mm][i * 4];
                fma2(acc0[i * 2 + 0], v.x, ss0);
                fma2(acc0[i * 2 + 1], v.y, ss0);
                fma2(acc1[i * 2 + 0], v.x, ss1);
                fma2(acc1[i * 2 + 1], v.y, ss1);
            }
        }
    }

    float* P0 = g_P + (((size_t)ms * BATCH + b) * NSP + n0) * NC;
    float* P1 = g_P + (((size_t)ms * BATCH + b) * NSP + n1) * NC;
    #pragma unroll
    for (int i = 0; i < 8; i++) {
        float2 a0 = unpack2(acc0[i * 2]), a1 = unpack2(acc0[i * 2 + 1]);
        *(float4*)(P0 + i * 4) = make_float4(a0.x, a0.y, a1.x, a1.y);
        float2 b0 = unpack2(acc1[i * 2]), b1 = unpack2(acc1[i * 2 + 1]);
        *(float4*)(P1 + i * 4) = make_float4(b0.x, b0.y, b1.x, b1.y);
    }
}

// ============================================================
// 5) y = gamma * sum_splits(P) + x   (deterministic reduce)
// ============================================================
__global__ __launch_bounds__(256) void finish_kernel(
    const float* __restrict__ x, const float* __restrict__ gamma,
    float* __restrict__ out)
{
    int i = blockIdx.x * 256 + threadIdx.x;  // 0 .. B*N*C-1
    float g = gamma[0];
    float sum = 0.f;
    #pragma unroll
    for (int s = 0; s < MSPLIT; s++) sum += g_P[(size_t)s * (BATCH * NSP * NC) + i];
    out[i] = g * sum + x[i];
}

// ============================================================
extern "C" void kernel_launch(void* const* d_in, const int* in_sizes, int n_in,
                              void* d_out, int out_size)
{
    const float* x     = (const float*)d_in[0];
    const float* gamma = (const float*)d_in[1];
    const float* qw = (const float*)d_in[2];
    const float* qb = (const float*)d_in[3];
    const float* qs = (const float*)d_in[4];
    const float* qo = (const float*)d_in[5];
    const float* kw = (const float*)d_in[6];
    const float* kb = (const float*)d_in[7];
    const float* ks = (const float*)d_in[8];
    const float* ko = (const float*)d_in[9];
    const float* jw = (const float*)d_in[10];
    const float* jb = (const float*)d_in[11];
    const float* js = (const float*)d_in[12];
    const float* jo = (const float*)d_in[13];
    const float* vw = (const float*)d_in[14];
    const float* vb = (const float*)d_in[15];
    const float* vs = (const float*)d_in[16];
    const float* vo = (const float*)d_in[17];
    float* out = (float*)d_out;

    proj_kernel<<<dim3(16, 16, BATCH), 128>>>(x, qw, qb, qs, qo,
                                              kw, kb, ks, ko,
                                              jw, jb, js, jo,
                                              vw, vb, vs, vo);
    m_kernel<<<dim3(8, 8, BATCH), 256>>>();
    r_kernel<<<(BATCH * NSP) / 256, 256>>>();
    attn_kernel<<<dim3(MSPLIT, NSP / TILE_N, BATCH), 128>>>();
    finish_kernel<<<(BATCH * NSP * NC) / 256, 256>>>(x, gamma, out);
}

// round 3
// speedup vs baseline: 1.5042x; 1.3542x over previous
#include <cuda_runtime.h>
#include <cuda_bf16.h>

// SpatialAttention, factored: m1@m2 = Qt(K Jt)K -> rank-8 bilinear form.
// R2: attn uses HMMA (mma.sync m16n8k16 bf16) for S*V; fp32 packed dot + tanh sigmoid.

#define BATCH 2
#define NSP   4096
#define NC    32
#define MSPLIT 8
#define MT    64
#define BLK_ROWS 64          // 4 warps x 16 rows

typedef unsigned long long ull;
typedef unsigned int u32;

// ---- scratch ----
__device__ float g_Q[BATCH * NSP * 8];
__device__ float g_K[BATCH * NSP * 8];
__device__ float g_J[BATCH * NSP * 8];
__device__ __nv_bfloat16 g_Vt[BATCH * NC * NSP];   // [b][c][n] bf16
__device__ float g_M[BATCH * 64];
__device__ float g_R[BATCH * NSP * 8];             // pre-scaled by 0.5
__device__ float g_P[MSPLIT * BATCH * NSP * NC];

#define XIDX(b,w,d,h,c) (((((((b)*16+(w))*16+(d))*16)+(h))*32)+(c))

__device__ __forceinline__ ull pack2(float lo, float hi) {
    ull r; asm("mov.b64 %0, {%1, %2};" : "=l"(r) : "f"(lo), "f"(hi)); return r;
}
__device__ __forceinline__ float2 unpack2(ull v) {
    float2 r; asm("mov.b64 {%0, %1}, %2;" : "=f"(r.x), "=f"(r.y) : "l"(v)); return r;
}
__device__ __forceinline__ ull mul2(ull a, ull b) {
    ull r; asm("mul.rn.f32x2 %0, %1, %2;" : "=l"(r) : "l"(a), "l"(b)); return r;
}
__device__ __forceinline__ void fma2(ull& acc, ull a, ull b) {
    asm("fma.rn.f32x2 %0, %1, %2, %3;" : "=l"(acc) : "l"(a), "l"(b), "l"(acc));
}
__device__ __forceinline__ float tanh_ap(float x) {
    float r; asm("tanh.approx.f32 %0, %1;" : "=f"(r) : "f"(x)); return r;
}
__device__ __forceinline__ u32 cvt_bf2(float hi, float lo) {
    u32 r; asm("cvt.rn.bf16x2.f32 %0, %1, %2;" : "=r"(r) : "f"(hi), "f"(lo)); return r;
}
__device__ __forceinline__ void mma16816(float* c, const u32* a, u32 b0, u32 b1) {
    asm("mma.sync.aligned.m16n8k16.row.col.f32.bf16.bf16.f32 "
        "{%0,%1,%2,%3}, {%4,%5,%6,%7}, {%8,%9}, {%0,%1,%2,%3};"
        : "+f"(c[0]), "+f"(c[1]), "+f"(c[2]), "+f"(c[3])
        : "r"(a[0]), "r"(a[1]), "r"(a[2]), "r"(a[3]), "r"(b0), "r"(b1));
}

// ============================================================
// 1) Projections
// ============================================================
__global__ __launch_bounds__(128) void proj_kernel(
    const float* __restrict__ x,
    const float* __restrict__ qw, const float* __restrict__ qb,
    const float* __restrict__ qs, const float* __restrict__ qo,
    const float* __restrict__ kw, const float* __restrict__ kb,
    const float* __restrict__ ks, const float* __restrict__ ko,
    const float* __restrict__ jw, const float* __restrict__ jb,
    const float* __restrict__ js, const float* __restrict__ jo,
    const float* __restrict__ vw, const float* __restrict__ vb,
    const float* __restrict__ vs, const float* __restrict__ vo)
{
    int d = blockIdx.x, w = blockIdx.y, b = blockIdx.z;
    int tid = threadIdx.x;

    __shared__ float s_c[18][33];
    __shared__ float s_dm[16][33], s_dp[16][33];
    __shared__ float s_wm[16][33], s_wp[16][33];
    __shared__ float s_qw[3][32][8], s_kw[3][32][8], s_jw[3][32][8];
    __shared__ float s_vw[32][32];

    for (int i = tid; i < 768; i += 128) {
        (&s_qw[0][0][0])[i] = qw[i];
        (&s_kw[0][0][0])[i] = kw[i];
        (&s_jw[0][0][0])[i] = jw[i];
    }
    for (int i = tid; i < 1024; i += 128) (&s_vw[0][0])[i] = vw[i];

    for (int i = tid; i < 512; i += 128) {
        int h = i >> 5, c = i & 31;
        s_c [h + 1][c] = x[XIDX(b, w, d, h, c)];
        s_dm[h][c] = (d > 0)  ? x[XIDX(b, w, d - 1, h, c)] : 0.f;
        s_dp[h][c] = (d < 15) ? x[XIDX(b, w, d + 1, h, c)] : 0.f;
        s_wm[h][c] = (w > 0)  ? x[XIDX(b, w - 1, d, h, c)] : 0.f;
        s_wp[h][c] = (w < 15) ? x[XIDX(b, w + 1, d, h, c)] : 0.f;
    }
    if (tid < 32)              s_c[0][tid]       = 0.f;
    else if (tid < 64)         s_c[17][tid - 32] = 0.f;
    __syncthreads();

    int h = tid >> 3, oc = tid & 7;
    float q = 0.f, k = 0.f, j = 0.f;
    float v0 = 0.f, v1 = 0.f, v2 = 0.f, v3 = 0.f;
    #pragma unroll
    for (int ci = 0; ci < 32; ci++) {
        float xc  = s_c [h + 1][ci];
        float xdm = s_dm[h][ci], xdp = s_dp[h][ci];
        float xwm = s_wm[h][ci], xwp = s_wp[h][ci];
        float xhm = s_c [h][ci], xhp = s_c [h + 2][ci];
        q += xdm * s_qw[0][ci][oc] + xc * s_qw[1][ci][oc] + xdp * s_qw[2][ci][oc];
        k += xwm * s_kw[0][ci][oc] + xc * s_kw[1][ci][oc] + xwp * s_kw[2][ci][oc];
        j += xhm * s_jw[0][ci][oc] + xc * s_jw[1][ci][oc] + xhp * s_jw[2][ci][oc];
        v0 += xc * s_vw[ci][oc];
        v1 += xc * s_vw[ci][oc + 8];
        v2 += xc * s_vw[ci][oc + 16];
        v3 += xc * s_vw[ci][oc + 24];
    }

    int n = w * 256 + d * 16 + h;
    g_Q[b * (NSP * 8) + n * 8 + oc] = fmaxf((q + qb[oc]) * qs[oc] + qo[oc], 0.f);
    g_K[b * (NSP * 8) + n * 8 + oc] = fmaxf((k + kb[oc]) * ks[oc] + ko[oc], 0.f);
    g_J[b * (NSP * 8) + n * 8 + oc] = fmaxf((j + jb[oc]) * js[oc] + jo[oc], 0.f);
    float vv[4] = {v0, v1, v2, v3};
    #pragma unroll
    for (int p = 0; p < 4; p++) {
        int co = oc + 8 * p;
        float val = fmaxf((vv[p] + vb[co]) * vs[co] + vo[co], 0.f);
        g_Vt[b * (NSP * NC) + co * NSP + n] = __float2bfloat16(val);
    }
}

// ============================================================
// 2) M[a][j] = sum_n K[a][n] * J[j][n]
// ============================================================
__global__ __launch_bounds__(256) void m_kernel()
{
    int a = blockIdx.x, j = blockIdx.y, b = blockIdx.z;
    const float* K = g_K + b * (NSP * 8) + a * NSP;
    const float* J = g_J + b * (NSP * 8) + j * NSP;
    float p = 0.f;
    for (int n = threadIdx.x; n < NSP; n += 256) p += K[n] * J[n];
    __shared__ float red[256];
    red[threadIdx.x] = p;
    __syncthreads();
    for (int s = 128; s > 0; s >>= 1) {
        if (threadIdx.x < s) red[threadIdx.x] += red[threadIdx.x + s];
        __syncthreads();
    }
    if (threadIdx.x == 0) g_M[b * 64 + a * 8 + j] = red[0];
}

// ============================================================
// 3) R[n][j] = 0.5 * sum_a Q[a][n] * M[a][j]   (0.5 folded for tanh sigmoid)
// ============================================================
__global__ __launch_bounds__(256) void r_kernel()
{
    int g = blockIdx.x * 256 + threadIdx.x;
    int b = g >> 12, n = g & (NSP - 1);
    float q[8];
    #pragma unroll
    for (int a = 0; a < 8; a++) q[a] = g_Q[b * (NSP * 8) + a * NSP + n];
    #pragma unroll
    for (int j = 0; j < 8; j++) {
        float r = 0.f;
        #pragma unroll
        for (int a = 0; a < 8; a++) r += q[a] * g_M[b * 64 + a * 8 + j];
        g_R[b * (NSP * 8) + n * 8 + j] = 0.5f * r;
    }
}

// ============================================================
// 4) attn: per block 64 rows x 512 m. A-fragment sigmoids in regs -> HMMA.
// ============================================================
#define KSTRIDE 10            // ull stride (80B, 16B aligned, conflict-free)
#define VSTRIDE 88            // bf16 stride (176B, 16B aligned, conflict-free)

__global__ __launch_bounds__(128) void attn_kernel()
{
    int ms = blockIdx.x, rt = blockIdx.y, b = blockIdx.z;
    int tid = threadIdx.x, wid = tid >> 5, l = tid & 31;
    int lq = l & 3;           // quad lane
    int lr = l >> 2;          // 0..7

    int row0 = rt * BLK_ROWS + wid * 16 + lr;   // fragment row (lane/4)
    int row1 = row0 + 8;

    const float* Rb = g_R + b * (NSP * 8);
    ull Rp[8];
    #pragma unroll
    for (int j = 0; j < 8; j++)
        Rp[j] = pack2(Rb[row0 * 8 + j], Rb[row1 * 8 + j]);

    float acc[16];
    #pragma unroll
    for (int i = 0; i < 16; i++) acc[i] = 0.f;

    __shared__ ull sK[MT][KSTRIDE];                    // [m][j] duplicated {k,k}
    __shared__ __nv_bfloat16 sV[NC][VSTRIDE];          // [c][m]

    const float* Kb = g_K + b * (NSP * 8);
    const __nv_bfloat16* Vtb = g_Vt + b * (NSP * NC);

    const int mbeg = ms * (NSP / MSPLIT);
    const int mend = mbeg + (NSP / MSPLIT);

    for (int mb = mbeg; mb < mend; mb += MT) {
        __syncthreads();
        // fill K tile (duplicated pairs): tid -> j = tid>>4, 4 m's
        {
            int j = tid >> 4, mg = (tid & 15) * 4;
            float4 kv = *(const float4*)(Kb + j * NSP + mb + mg);
            sK[mg + 0][j] = pack2(kv.x, kv.x);
            sK[mg + 1][j] = pack2(kv.y, kv.y);
            sK[mg + 2][j] = pack2(kv.z, kv.z);
            sK[mg + 3][j] = pack2(kv.w, kv.w);
        }
        // fill V tile: 32c x 64m bf16, 8-elt vectors
        #pragma unroll
        for (int i = tid; i < 256; i += 128) {
            int c = i >> 3, mg = (i & 7) * 8;
            uint4 v = *(const uint4*)(Vtb + c * NSP + mb + mg);
            *(uint4*)&sV[c][mg] = v;
        }
        __syncthreads();

        #pragma unroll
        for (int ch = 0; ch < 4; ch++) {
            int cb = ch * 16;
            int m0 = cb + lq * 2;
            float sg[2][4];
            #pragma unroll
            for (int mi = 0; mi < 4; mi++) {
                int m = m0 + (mi & 1) + ((mi >> 1) << 3);
                const ulonglong2* kp = (const ulonglong2*)&sK[m][0];
                ulonglong2 k01 = kp[0], k23 = kp[1], k45 = kp[2], k67 = kp[3];
                ull t = mul2(Rp[0], k01.x);
                fma2(t, Rp[1], k01.y);
                fma2(t, Rp[2], k23.x);
                fma2(t, Rp[3], k23.y);
                fma2(t, Rp[4], k45.x);
                fma2(t, Rp[5], k45.y);
                fma2(t, Rp[6], k67.x);
                fma2(t, Rp[7], k67.y);
                float2 tf = unpack2(t);
                sg[0][mi] = __fmaf_rn(tanh_ap(tf.x), 0.5f, 0.5f);
                sg[1][mi] = __fmaf_rn(tanh_ap(tf.y), 0.5f, 0.5f);
            }
            u32 A[4];
            A[0] = cvt_bf2(sg[0][1], sg[0][0]);
            A[1] = cvt_bf2(sg[1][1], sg[1][0]);
            A[2] = cvt_bf2(sg[0][3], sg[0][2]);
            A[3] = cvt_bf2(sg[1][3], sg[1][2]);
            #pragma unroll
            for (int g = 0; g < 4; g++) {
                int c = g * 8 + lr;
                u32 b0 = *(const u32*)&sV[c][m0];
                u32 b1 = *(const u32*)&sV[c][m0 + 8];
                mma16816(acc + g * 4, A, b0, b1);
            }
        }
    }

    // epilogue: write partials
    float* P = g_P + ((size_t)(ms * BATCH + b) * NSP) * NC;
    #pragma unroll
    for (int g = 0; g < 4; g++) {
        int col = g * 8 + lq * 2;
        *(float2*)(P + row0 * NC + col) = make_float2(acc[g * 4 + 0], acc[g * 4 + 1]);
        *(float2*)(P + row1 * NC + col) = make_float2(acc[g * 4 + 2], acc[g * 4 + 3]);
    }
}

// ============================================================
// 5) y = gamma * sum_splits(P) + x
// ============================================================
__global__ __launch_bounds__(256) void finish_kernel(
    const float* __restrict__ x, const float* __restrict__ gamma,
    float* __restrict__ out)
{
    int i = blockIdx.x * 256 + threadIdx.x;
    float g = gamma[0];
    float sum = 0.f;
    #pragma unroll
    for (int s = 0; s < MSPLIT; s++) sum += g_P[(size_t)s * (BATCH * NSP * NC) + i];
    out[i] = g * sum + x[i];
}

// ============================================================
extern "C" void kernel_launch(void* const* d_in, const int* in_sizes, int n_in,
                              void* d_out, int out_size)
{
    const float* x     = (const float*)d_in[0];
    const float* gamma = (const float*)d_in[1];
    const float* qw = (const float*)d_in[2];
    const float* qb = (const float*)d_in[3];
    const float* qs = (const float*)d_in[4];
    const float* qo = (const float*)d_in[5];
    const float* kw = (const float*)d_in[6];
    const float* kb = (const float*)d_in[7];
    const float* ks = (const float*)d_in[8];
    const float* ko = (const float*)d_in[9];
    const float* jw = (const float*)d_in[10];
    const float* jb = (const float*)d_in[11];
    const float* js = (const float*)d_in[12];
    const float* jo = (const float*)d_in[13];
    const float* vw = (const float*)d_in[14];
    const float* vb = (const float*)d_in[15];
    const float* vs = (const float*)d_in[16];
    const float* vo = (const float*)d_in[17];
    float* out = (float*)d_out;

    proj_kernel<<<dim3(16, 16, BATCH), 128>>>(x, qw, qb, qs, qo,
                                              kw, kb, ks, ko,
                                              jw, jb, js, jo,
                                              vw, vb, vs, vo);
    m_kernel<<<dim3(8, 8, BATCH), 256>>>();
    r_kernel<<<(BATCH * NSP) / 256, 256>>>();
    attn_kernel<<<dim3(MSPLIT, NSP / BLK_ROWS, BATCH), 128>>>();
    finish_kernel<<<(BATCH * NSP * NC) / 256, 256>>>(x, gamma, out);
}

// round 4
// speedup vs baseline: 3.0757x; 2.0448x over previous
#include <cuda_runtime.h>
#include <cuda_bf16.h>

// SpatialAttention, factored: m1@m2 = Qt(K Jt)K -> rank-8 bilinear form.
// R3: t = R.K on tf32 MMA (m16n8k8), sigmoid in regs, S.V on bf16 HMMA.
//     R computed inline in attn (r_kernel removed).

#define BATCH 2
#define NSP   4096
#define NC    32
#define MSPLIT 4
#define MT    64
#define BLK_ROWS 64          // 4 warps x 16 rows

typedef unsigned long long ull;
typedef unsigned int u32;

// ---- scratch ----
__device__ float g_Q[BATCH * NSP * 8];
__device__ float g_K[BATCH * NSP * 8];
__device__ float g_J[BATCH * NSP * 8];
__device__ __nv_bfloat16 g_Vt[BATCH * NC * NSP];   // [b][c][n] bf16
__device__ float g_M[BATCH * 64];                  // 0.5 * (K Jt), [a*8+j]
__device__ float g_P[MSPLIT * BATCH * NSP * NC];

#define XIDX(b,w,d,h,c) (((((((b)*16+(w))*16+(d))*16)+(h))*32)+(c))

__device__ __forceinline__ float tanh_ap(float x) {
    float r; asm("tanh.approx.f32 %0, %1;" : "=f"(r) : "f"(x)); return r;
}
__device__ __forceinline__ u32 cvt_bf2(float hi, float lo) {
    u32 r; asm("cvt.rn.bf16x2.f32 %0, %1, %2;" : "=r"(r) : "f"(hi), "f"(lo)); return r;
}
__device__ __forceinline__ u32 tf32c(float x) {
    u32 r; asm("cvt.rna.tf32.f32 %0, %1;" : "=r"(r) : "f"(x)); return r;
}
__device__ __forceinline__ void mma_tf32(float* c, const u32* a, u32 b0, u32 b1) {
    asm("mma.sync.aligned.m16n8k8.row.col.f32.tf32.tf32.f32 "
        "{%0,%1,%2,%3}, {%4,%5,%6,%7}, {%8,%9}, {%0,%1,%2,%3};"
        : "+f"(c[0]), "+f"(c[1]), "+f"(c[2]), "+f"(c[3])
        : "r"(a[0]), "r"(a[1]), "r"(a[2]), "r"(a[3]), "r"(b0), "r"(b1));
}
__device__ __forceinline__ void mma16816(float* c, const u32* a, u32 b0, u32 b1) {
    asm("mma.sync.aligned.m16n8k16.row.col.f32.bf16.bf16.f32 "
        "{%0,%1,%2,%3}, {%4,%5,%6,%7}, {%8,%9}, {%0,%1,%2,%3};"
        : "+f"(c[0]), "+f"(c[1]), "+f"(c[2]), "+f"(c[3])
        : "r"(a[0]), "r"(a[1]), "r"(a[2]), "r"(a[3]), "r"(b0), "r"(b1));
}

// ============================================================
// 1) Projections
// ============================================================
__global__ __launch_bounds__(128) void proj_kernel(
    const float* __restrict__ x,
    const float* __restrict__ qw, const float* __restrict__ qb,
    const float* __restrict__ qs, const float* __restrict__ qo,
    const float* __restrict__ kw, const float* __restrict__ kb,
    const float* __restrict__ ks, const float* __restrict__ ko,
    const float* __restrict__ jw, const float* __restrict__ jb,
    const float* __restrict__ js, const float* __restrict__ jo,
    const float* __restrict__ vw, const float* __restrict__ vb,
    const float* __restrict__ vs, const float* __restrict__ vo)
{
    int d = blockIdx.x, w = blockIdx.y, b = blockIdx.z;
    int tid = threadIdx.x;

    __shared__ float s_c[18][33];
    __shared__ float s_dm[16][33], s_dp[16][33];
    __shared__ float s_wm[16][33], s_wp[16][33];
    __shared__ float s_qw[3][32][8], s_kw[3][32][8], s_jw[3][32][8];
    __shared__ float s_vw[32][32];

    for (int i = tid; i < 768; i += 128) {
        (&s_qw[0][0][0])[i] = qw[i];
        (&s_kw[0][0][0])[i] = kw[i];
        (&s_jw[0][0][0])[i] = jw[i];
    }
    for (int i = tid; i < 1024; i += 128) (&s_vw[0][0])[i] = vw[i];

    for (int i = tid; i < 512; i += 128) {
        int h = i >> 5, c = i & 31;
        s_c [h + 1][c] = x[XIDX(b, w, d, h, c)];
        s_dm[h][c] = (d > 0)  ? x[XIDX(b, w, d - 1, h, c)] : 0.f;
        s_dp[h][c] = (d < 15) ? x[XIDX(b, w, d + 1, h, c)] : 0.f;
        s_wm[h][c] = (w > 0)  ? x[XIDX(b, w - 1, d, h, c)] : 0.f;
        s_wp[h][c] = (w < 15) ? x[XIDX(b, w + 1, d, h, c)] : 0.f;
    }
    if (tid < 32)              s_c[0][tid]       = 0.f;
    else if (tid < 64)         s_c[17][tid - 32] = 0.f;
    __syncthreads();

    int h = tid >> 3, oc = tid & 7;
    float q = 0.f, k = 0.f, j = 0.f;
    float v0 = 0.f, v1 = 0.f, v2 = 0.f, v3 = 0.f;
    #pragma unroll
    for (int ci = 0; ci < 32; ci++) {
        float xc  = s_c [h + 1][ci];
        float xdm = s_dm[h][ci], xdp = s_dp[h][ci];
        float xwm = s_wm[h][ci], xwp = s_wp[h][ci];
        float xhm = s_c [h][ci], xhp = s_c [h + 2][ci];
        q += xdm * s_qw[0][ci][oc] + xc * s_qw[1][ci][oc] + xdp * s_qw[2][ci][oc];
        k += xwm * s_kw[0][ci][oc] + xc * s_kw[1][ci][oc] + xwp * s_kw[2][ci][oc];
        j += xhm * s_jw[0][ci][oc] + xc * s_jw[1][ci][oc] + xhp * s_jw[2][ci][oc];
        v0 += xc * s_vw[ci][oc];
        v1 += xc * s_vw[ci][oc + 8];
        v2 += xc * s_vw[ci][oc + 16];
        v3 += xc * s_vw[ci][oc + 24];
    }

    int n = w * 256 + d * 16 + h;
    g_Q[b * (NSP * 8) + n * 8 + oc] = fmaxf((q + qb[oc]) * qs[oc] + qo[oc], 0.f);
    g_K[b * (NSP * 8) + n * 8 + oc] = fmaxf((k + kb[oc]) * ks[oc] + ko[oc], 0.f);
    g_J[b * (NSP * 8) + n * 8 + oc] = fmaxf((j + jb[oc]) * js[oc] + jo[oc], 0.f);
    float vv[4] = {v0, v1, v2, v3};
    #pragma unroll
    for (int p = 0; p < 4; p++) {
        int co = oc + 8 * p;
        float val = fmaxf((vv[p] + vb[co]) * vs[co] + vo[co], 0.f);
        g_Vt[b * (NSP * NC) + co * NSP + n] = __float2bfloat16(val);
    }
}

// ============================================================
// 2) M[a][j] = 0.5 * sum_n K[a][n] * J[j][n]   (0.5 folded for tanh sigmoid)
// ============================================================
__global__ __launch_bounds__(256) void m_kernel()
{
    int a = blockIdx.x, j = blockIdx.y, b = blockIdx.z;
    const float* K = g_K + b * (NSP * 8) + a * NSP;
    const float* J = g_J + b * (NSP * 8) + j * NSP;
    float p = 0.f;
    for (int n = threadIdx.x; n < NSP; n += 256) p += K[n] * J[n];
    __shared__ float red[256];
    red[threadIdx.x] = p;
    __syncthreads();
    for (int s = 128; s > 0; s >>= 1) {
        if (threadIdx.x < s) red[threadIdx.x] += red[threadIdx.x + s];
        __syncthreads();
    }
    if (threadIdx.x == 0) g_M[b * 64 + a * 8 + j] = 0.5f * red[0];
}

// ============================================================
// 3) attn: R inline; t via tf32 MMA; sigmoid in regs; S.V via bf16 HMMA.
// ============================================================
__global__ __launch_bounds__(128) void attn_kernel()
{
    int ms = blockIdx.x, rt = blockIdx.y, b = blockIdx.z;
    int tid = threadIdx.x, wid = tid >> 5, l = tid & 31;
    int lq = l & 3, lr = l >> 2;
    int rowbase = rt * BLK_ROWS;
    int row0 = rowbase + wid * 16 + lr, row1 = row0 + 8;

    __shared__ float sQ[8][64];
    __shared__ float sM[64];
    __shared__ u32 sKt[8][72];                 // tf32, stride 72 (conflict-free)
    __shared__ __nv_bfloat16 sV[NC][72];       // bf16, stride 72

    const float* Qb = g_Q + b * (NSP * 8);
    if (tid < 64) sM[tid] = g_M[b * 64 + tid];
    {
        int a = tid >> 4, i = (tid & 15) * 4;
        *(float4*)&sQ[a][i] = *(const float4*)(Qb + a * NSP + rowbase + i);
    }
    __syncthreads();

    // R fragment for tf32 MMA: a0=(row0,lq) a1=(row1,lq) a2=(row0,lq+4) a3=(row1,lq+4)
    float r00 = 0.f, r01 = 0.f, r10 = 0.f, r11 = 0.f;
    int i0 = wid * 16 + lr, i1 = i0 + 8;
    #pragma unroll
    for (int a = 0; a < 8; a++) {
        float q0 = sQ[a][i0], q1 = sQ[a][i1];
        r00 += q0 * sM[a * 8 + lq];
        r01 += q0 * sM[a * 8 + lq + 4];
        r10 += q1 * sM[a * 8 + lq];
        r11 += q1 * sM[a * 8 + lq + 4];
    }
    u32 A32[4] = { tf32c(r00), tf32c(r10), tf32c(r01), tf32c(r11) };

    float acc[16];
    #pragma unroll
    for (int i = 0; i < 16; i++) acc[i] = 0.f;

    const float* Kb = g_K + b * (NSP * 8);
    const __nv_bfloat16* Vtb = g_Vt + b * (NSP * NC);

    const int mbeg = ms * (NSP / MSPLIT);
    const int mend = mbeg + (NSP / MSPLIT);

    for (int mb = mbeg; mb < mend; mb += MT) {
        __syncthreads();
        {   // K tile -> tf32
            int j = tid >> 4, mg = (tid & 15) * 4;
            float4 kv = *(const float4*)(Kb + j * NSP + mb + mg);
            uint4 kt = make_uint4(tf32c(kv.x), tf32c(kv.y), tf32c(kv.z), tf32c(kv.w));
            *(uint4*)&sKt[j][mg] = kt;
        }
        #pragma unroll
        for (int i = tid; i < 256; i += 128) {   // V tile
            int c = i >> 3, mg = (i & 7) * 8;
            *(uint4*)&sV[c][mg] = *(const uint4*)(Vtb + c * NSP + mb + mg);
        }
        __syncthreads();

        #pragma unroll
        for (int ch = 0; ch < 4; ch++) {
            int cb = ch * 16;
            u32 kb0a = sKt[lq][cb + lr],     kb1a = sKt[lq + 4][cb + lr];
            u32 kb0b = sKt[lq][cb + 8 + lr], kb1b = sKt[lq + 4][cb + 8 + lr];
            float t[8];
            #pragma unroll
            for (int i = 0; i < 8; i++) t[i] = 0.f;
            mma_tf32(t,     A32, kb0a, kb1a);    // cols cb..cb+7
            mma_tf32(t + 4, A32, kb0b, kb1b);    // cols cb+8..cb+15

            float s0 = __fmaf_rn(tanh_ap(t[0]), 0.5f, 0.5f);
            float s1 = __fmaf_rn(tanh_ap(t[1]), 0.5f, 0.5f);
            float s2 = __fmaf_rn(tanh_ap(t[2]), 0.5f, 0.5f);
            float s3 = __fmaf_rn(tanh_ap(t[3]), 0.5f, 0.5f);
            float s4 = __fmaf_rn(tanh_ap(t[4]), 0.5f, 0.5f);
            float s5 = __fmaf_rn(tanh_ap(t[5]), 0.5f, 0.5f);
            float s6 = __fmaf_rn(tanh_ap(t[6]), 0.5f, 0.5f);
            float s7 = __fmaf_rn(tanh_ap(t[7]), 0.5f, 0.5f);

            u32 Abf[4];
            Abf[0] = cvt_bf2(s1, s0);   // (row0, m0),(row0, m0+1)
            Abf[1] = cvt_bf2(s3, s2);   // row1
            Abf[2] = cvt_bf2(s5, s4);   // (row0, m0+8),(row0, m0+9)
            Abf[3] = cvt_bf2(s7, s6);   // row1

            int m0 = cb + 2 * lq;
            #pragma unroll
            for (int g = 0; g < 4; g++) {
                int c = g * 8 + lr;
                u32 vb0 = *(const u32*)&sV[c][m0];
                u32 vb1 = *(const u32*)&sV[c][m0 + 8];
                mma16816(acc + g * 4, Abf, vb0, vb1);
            }
        }
    }

    float* P = g_P + ((size_t)(ms * BATCH + b) * NSP) * NC;
    #pragma unroll
    for (int g = 0; g < 4; g++) {
        int col = g * 8 + lq * 2;
        *(float2*)(P + row0 * NC + col) = make_float2(acc[g * 4 + 0], acc[g * 4 + 1]);
        *(float2*)(P + row1 * NC + col) = make_float2(acc[g * 4 + 2], acc[g * 4 + 3]);
    }
}

// ============================================================
// 4) y = gamma * sum_splits(P) + x
// ============================================================
__global__ __launch_bounds__(256) void finish_kernel(
    const float* __restrict__ x, const float* __restrict__ gamma,
    float* __restrict__ out)
{
    int i = blockIdx.x * 256 + threadIdx.x;
    float g = gamma[0];
    float sum = 0.f;
    #pragma unroll
    for (int s = 0; s < MSPLIT; s++) sum += g_P[(size_t)s * (BATCH * NSP * NC) + i];
    out[i] = g * sum + x[i];
}

// ============================================================
extern "C" void kernel_launch(void* const* d_in, const int* in_sizes, int n_in,
                              void* d_out, int out_size)
{
    const float* x     = (const float*)d_in[0];
    const float* gamma = (const float*)d_in[1];
    const float* qw = (const float*)d_in[2];
    const float* qb = (const float*)d_in[3];
    const float* qs = (const float*)d_in[4];
    const float* qo = (const float*)d_in[5];
    const float* kw = (const float*)d_in[6];
    const float* kb = (const float*)d_in[7];
    const float* ks = (const float*)d_in[8];
    const float* ko = (const float*)d_in[9];
    const float* jw = (const float*)d_in[10];
    const float* jb = (const float*)d_in[11];
    const float* js = (const float*)d_in[12];
    const float* jo = (const float*)d_in[13];
    const float* vw = (const float*)d_in[14];
    const float* vb = (const float*)d_in[15];
    const float* vs = (const float*)d_in[16];
    const float* vo = (const float*)d_in[17];
    float* out = (float*)d_out;

    proj_kernel<<<dim3(16, 16, BATCH), 128>>>(x, qw, qb, qs, qo,
                                              kw, kb, ks, ko,
                                              jw, jb, js, jo,
                                              vw, vb, vs, vo);
    m_kernel<<<dim3(8, 8, BATCH), 256>>>();
    attn_kernel<<<dim3(MSPLIT, NSP / BLK_ROWS, BATCH), 128>>>();
    finish_kernel<<<(BATCH * NSP * NC) / 256, 256>>>(x, gamma, out);
}

// round 5
// speedup vs baseline: 3.4160x; 1.1106x over previous
#include <cuda_runtime.h>
#include <cuda_bf16.h>

// SpatialAttention, factored: m1@m2 = Qt(K Jt)K -> rank-8 bilinear form.
// R4: attn double-buffers K/V tiles via cp.async (raw fp32 -> tf32 MMA),
//     finish kernel vectorized float4.

#define BATCH 2
#define NSP   4096
#define NC    32
#define MSPLIT 4
#define MT    64
#define BLK_ROWS 64          // 4 warps x 16 rows

typedef unsigned long long ull;
typedef unsigned int u32;

// ---- scratch ----
__device__ float g_Q[BATCH * NSP * 8];
__device__ float g_K[BATCH * NSP * 8];
__device__ float g_J[BATCH * NSP * 8];
__device__ __nv_bfloat16 g_Vt[BATCH * NC * NSP];   // [b][c][n] bf16
__device__ float g_M[BATCH * 64];                  // 0.5 * (K Jt)
__device__ float g_P[MSPLIT * BATCH * NSP * NC];

#define XIDX(b,w,d,h,c) (((((((b)*16+(w))*16+(d))*16)+(h))*32)+(c))

__device__ __forceinline__ float tanh_ap(float x) {
    float r; asm("tanh.approx.f32 %0, %1;" : "=f"(r) : "f"(x)); return r;
}
__device__ __forceinline__ u32 cvt_bf2(float hi, float lo) {
    u32 r; asm("cvt.rn.bf16x2.f32 %0, %1, %2;" : "=r"(r) : "f"(hi), "f"(lo)); return r;
}
__device__ __forceinline__ u32 tf32c(float x) {
    u32 r; asm("cvt.rna.tf32.f32 %0, %1;" : "=r"(r) : "f"(x)); return r;
}
__device__ __forceinline__ void mma_tf32(float* c, const u32* a, u32 b0, u32 b1) {
    asm("mma.sync.aligned.m16n8k8.row.col.f32.tf32.tf32.f32 "
        "{%0,%1,%2,%3}, {%4,%5,%6,%7}, {%8,%9}, {%0,%1,%2,%3};"
        : "+f"(c[0]), "+f"(c[1]), "+f"(c[2]), "+f"(c[3])
        : "r"(a[0]), "r"(a[1]), "r"(a[2]), "r"(a[3]), "r"(b0), "r"(b1));
}
__device__ __forceinline__ void mma16816(float* c, const u32* a, u32 b0, u32 b1) {
    asm("mma.sync.aligned.m16n8k16.row.col.f32.bf16.bf16.f32 "
        "{%0,%1,%2,%3}, {%4,%5,%6,%7}, {%8,%9}, {%0,%1,%2,%3};"
        : "+f"(c[0]), "+f"(c[1]), "+f"(c[2]), "+f"(c[3])
        : "r"(a[0]), "r"(a[1]), "r"(a[2]), "r"(a[3]), "r"(b0), "r"(b1));
}
__device__ __forceinline__ void cp16(void* smem_dst, const void* gsrc) {
    u32 d = (u32)__cvta_generic_to_shared(smem_dst);
    asm volatile("cp.async.ca.shared.global [%0], [%1], 16;" :: "r"(d), "l"(gsrc));
}

// ============================================================
// 1) Projections
// ============================================================
__global__ __launch_bounds__(128) void proj_kernel(
    const float* __restrict__ x,
    const float* __restrict__ qw, const float* __restrict__ qb,
    const float* __restrict__ qs, const float* __restrict__ qo,
    const float* __restrict__ kw, const float* __restrict__ kb,
    const float* __restrict__ ks, const float* __restrict__ ko,
    const float* __restrict__ jw, const float* __restrict__ jb,
    const float* __restrict__ js, const float* __restrict__ jo,
    const float* __restrict__ vw, const float* __restrict__ vb,
    const float* __restrict__ vs, const float* __restrict__ vo)
{
    int d = blockIdx.x, w = blockIdx.y, b = blockIdx.z;
    int tid = threadIdx.x;

    __shared__ float s_c[18][33];
    __shared__ float s_dm[16][33], s_dp[16][33];
    __shared__ float s_wm[16][33], s_wp[16][33];
    __shared__ float s_qw[3][32][8], s_kw[3][32][8], s_jw[3][32][8];
    __shared__ float s_vw[32][32];

    for (int i = tid; i < 768; i += 128) {
        (&s_qw[0][0][0])[i] = qw[i];
        (&s_kw[0][0][0])[i] = kw[i];
        (&s_jw[0][0][0])[i] = jw[i];
    }
    for (int i = tid; i < 1024; i += 128) (&s_vw[0][0])[i] = vw[i];

    for (int i = tid; i < 512; i += 128) {
        int h = i >> 5, c = i & 31;
        s_c [h + 1][c] = x[XIDX(b, w, d, h, c)];
        s_dm[h][c] = (d > 0)  ? x[XIDX(b, w, d - 1, h, c)] : 0.f;
        s_dp[h][c] = (d < 15) ? x[XIDX(b, w, d + 1, h, c)] : 0.f;
        s_wm[h][c] = (w > 0)  ? x[XIDX(b, w - 1, d, h, c)] : 0.f;
        s_wp[h][c] = (w < 15) ? x[XIDX(b, w + 1, d, h, c)] : 0.f;
    }
    if (tid < 32)              s_c[0][tid]       = 0.f;
    else if (tid < 64)         s_c[17][tid - 32] = 0.f;
    __syncthreads();

    int h = tid >> 3, oc = tid & 7;
    float q = 0.f, k = 0.f, j = 0.f;
    float v0 = 0.f, v1 = 0.f, v2 = 0.f, v3 = 0.f;
    #pragma unroll
    for (int ci = 0; ci < 32; ci++) {
        float xc  = s_c [h + 1][ci];
        float xdm = s_dm[h][ci], xdp = s_dp[h][ci];
        float xwm = s_wm[h][ci], xwp = s_wp[h][ci];
        float xhm = s_c [h][ci], xhp = s_c [h + 2][ci];
        q += xdm * s_qw[0][ci][oc] + xc * s_qw[1][ci][oc] + xdp * s_qw[2][ci][oc];
        k += xwm * s_kw[0][ci][oc] + xc * s_kw[1][ci][oc] + xwp * s_kw[2][ci][oc];
        j += xhm * s_jw[0][ci][oc] + xc * s_jw[1][ci][oc] + xhp * s_jw[2][ci][oc];
        v0 += xc * s_vw[ci][oc];
        v1 += xc * s_vw[ci][oc + 8];
        v2 += xc * s_vw[ci][oc + 16];
        v3 += xc * s_vw[ci][oc + 24];
    }

    int n = w * 256 + d * 16 + h;
    g_Q[b * (NSP * 8) + n * 8 + oc] = fmaxf((q + qb[oc]) * qs[oc] + qo[oc], 0.f);
    g_K[b * (NSP * 8) + n * 8 + oc] = fmaxf((k + kb[oc]) * ks[oc] + ko[oc], 0.f);
    g_J[b * (NSP * 8) + n * 8 + oc] = fmaxf((j + jb[oc]) * js[oc] + jo[oc], 0.f);
    float vv[4] = {v0, v1, v2, v3};
    #pragma unroll
    for (int p = 0; p < 4; p++) {
        int co = oc + 8 * p;
        float val = fmaxf((vv[p] + vb[co]) * vs[co] + vo[co], 0.f);
        g_Vt[b * (NSP * NC) + co * NSP + n] = __float2bfloat16(val);
    }
}

// ============================================================
// 2) M[a][j] = 0.5 * sum_n K[a][n] * J[j][n]
// ============================================================
__global__ __launch_bounds__(256) void m_kernel()
{
    int a = blockIdx.x, j = blockIdx.y, b = blockIdx.z;
    const float* K = g_K + b * (NSP * 8) + a * NSP;
    const float* J = g_J + b * (NSP * 8) + j * NSP;
    float p = 0.f;
    for (int n = threadIdx.x; n < NSP; n += 256) p += K[n] * J[n];
    __shared__ float red[256];
    red[threadIdx.x] = p;
    __syncthreads();
    for (int s = 128; s > 0; s >>= 1) {
        if (threadIdx.x < s) red[threadIdx.x] += red[threadIdx.x + s];
        __syncthreads();
    }
    if (threadIdx.x == 0) g_M[b * 64 + a * 8 + j] = 0.5f * red[0];
}

// ============================================================
// 3) attn: R inline; t via tf32 MMA; sigmoid in regs; S.V via bf16 HMMA.
//    2-stage cp.async double buffer for K/V tiles.
// ============================================================
__global__ __launch_bounds__(128) void attn_kernel()
{
    int ms = blockIdx.x, rt = blockIdx.y, b = blockIdx.z;
    int tid = threadIdx.x, wid = tid >> 5, l = tid & 31;
    int lq = l & 3, lr = l >> 2;
    int rowbase = rt * BLK_ROWS;
    int row0 = rowbase + wid * 16 + lr, row1 = row0 + 8;

    __shared__ float sQ[8][64];
    __shared__ float sM[64];
    __shared__ u32 sKt[2][8][72];              // raw fp32 bits (tf32 by truncation)
    __shared__ __nv_bfloat16 sV[2][32][72];

    const float* Qb = g_Q + b * (NSP * 8);
    const float* Kb = g_K + b * (NSP * 8);
    const __nv_bfloat16* Vtb = g_Vt + b * (NSP * NC);

    if (tid < 64) sM[tid] = g_M[b * 64 + tid];
    {
        int a = tid >> 4, i = (tid & 15) * 4;
        *(float4*)&sQ[a][i] = *(const float4*)(Qb + a * NSP + rowbase + i);
    }

    const int mbeg = ms * (NSP / MSPLIT);
    const int NT = (NSP / MSPLIT) / MT;

    // tile fill lambda (cp.async, 16B chunks)
    int kj = tid >> 4, kmg = (tid & 15) * 4;       // K: 1 chunk/thread
    int vc0 = tid >> 3, vmg0 = (tid & 7) * 8;      // V: 2 chunks/thread
    int vc1 = (tid + 128) >> 3, vmg1 = vmg0;

    // prologue: stage 0
    cp16(&sKt[0][kj][kmg], Kb + kj * NSP + mbeg + kmg);
    cp16(&sV[0][vc0][vmg0], Vtb + vc0 * NSP + mbeg + vmg0);
    cp16(&sV[0][vc1][vmg1], Vtb + vc1 * NSP + mbeg + vmg1);
    asm volatile("cp.async.commit_group;");

    __syncthreads();   // sQ/sM ready

    // R fragment: a0=(row0,lq) a1=(row1,lq) a2=(row0,lq+4) a3=(row1,lq+4)
    float r00 = 0.f, r01 = 0.f, r10 = 0.f, r11 = 0.f;
    int i0 = wid * 16 + lr, i1 = i0 + 8;
    #pragma unroll
    for (int a = 0; a < 8; a++) {
        float q0 = sQ[a][i0], q1 = sQ[a][i1];
        r00 += q0 * sM[a * 8 + lq];
        r01 += q0 * sM[a * 8 + lq + 4];
        r10 += q1 * sM[a * 8 + lq];
        r11 += q1 * sM[a * 8 + lq + 4];
    }
    u32 A32[4] = { tf32c(r00), tf32c(r10), tf32c(r01), tf32c(r11) };

    float acc[16];
    #pragma unroll
    for (int i = 0; i < 16; i++) acc[i] = 0.f;

    for (int ti = 0; ti < NT; ti++) {
        int cur = ti & 1, nxt = cur ^ 1;
        __syncthreads();   // buffer nxt fully consumed (from iter ti-1)
        if (ti + 1 < NT) {
            int mb = mbeg + (ti + 1) * MT;
            cp16(&sKt[nxt][kj][kmg], Kb + kj * NSP + mb + kmg);
            cp16(&sV[nxt][vc0][vmg0], Vtb + vc0 * NSP + mb + vmg0);
            cp16(&sV[nxt][vc1][vmg1], Vtb + vc1 * NSP + mb + vmg1);
        }
        asm volatile("cp.async.commit_group;");
        asm volatile("cp.async.wait_group 1;");
        __syncthreads();   // buffer cur visible to all

        #pragma unroll
        for (int ch = 0; ch < 4; ch++) {
            int cb = ch * 16;
            u32 kb0a = sKt[cur][lq][cb + lr],     kb1a = sKt[cur][lq + 4][cb + lr];
            u32 kb0b = sKt[cur][lq][cb + 8 + lr], kb1b = sKt[cur][lq + 4][cb + 8 + lr];
            float t[8];
            #pragma unroll
            for (int i = 0; i < 8; i++) t[i] = 0.f;
            mma_tf32(t,     A32, kb0a, kb1a);
            mma_tf32(t + 4, A32, kb0b, kb1b);

            float s0 = __fmaf_rn(tanh_ap(t[0]), 0.5f, 0.5f);
            float s1 = __fmaf_rn(tanh_ap(t[1]), 0.5f, 0.5f);
            float s2 = __fmaf_rn(tanh_ap(t[2]), 0.5f, 0.5f);
            float s3 = __fmaf_rn(tanh_ap(t[3]), 0.5f, 0.5f);
            float s4 = __fmaf_rn(tanh_ap(t[4]), 0.5f, 0.5f);
            float s5 = __fmaf_rn(tanh_ap(t[5]), 0.5f, 0.5f);
            float s6 = __fmaf_rn(tanh_ap(t[6]), 0.5f, 0.5f);
            float s7 = __fmaf_rn(tanh_ap(t[7]), 0.5f, 0.5f);

            u32 Abf[4];
            Abf[0] = cvt_bf2(s1, s0);
            Abf[1] = cvt_bf2(s3, s2);
            Abf[2] = cvt_bf2(s5, s4);
            Abf[3] = cvt_bf2(s7, s6);

            int m0 = cb + 2 * lq;
            #pragma unroll
            for (int g = 0; g < 4; g++) {
                int c = g * 8 + lr;
                u32 vb0 = *(const u32*)&sV[cur][c][m0];
                u32 vb1 = *(const u32*)&sV[cur][c][m0 + 8];
                mma16816(acc + g * 4, Abf, vb0, vb1);
            }
        }
    }

    float* P = g_P + ((size_t)(ms * BATCH + b) * NSP) * NC;
    #pragma unroll
    for (int g = 0; g < 4; g++) {
        int col = g * 8 + lq * 2;
        *(float2*)(P + row0 * NC + col) = make_float2(acc[g * 4 + 0], acc[g * 4 + 1]);
        *(float2*)(P + row1 * NC + col) = make_float2(acc[g * 4 + 2], acc[g * 4 + 3]);
    }
}

// ============================================================
// 4) y = gamma * sum_splits(P) + x   (float4 vectorized)
// ============================================================
__global__ __launch_bounds__(256) void finish_kernel(
    const float* __restrict__ x, const float* __restrict__ gamma,
    float* __restrict__ out)
{
    int i4 = (blockIdx.x * 256 + threadIdx.x) * 4;
    float g = gamma[0];
    float4 s = *(const float4*)(g_P + i4);
    #pragma unroll
    for (int sp = 1; sp < MSPLIT; sp++) {
        float4 p = *(const float4*)(g_P + (size_t)sp * (BATCH * NSP * NC) + i4);
        s.x += p.x; s.y += p.y; s.z += p.z; s.w += p.w;
    }
    float4 xv = *(const float4*)(x + i4);
    *(float4*)(out + i4) = make_float4(g * s.x + xv.x, g * s.y + xv.y,
                                       g * s.z + xv.z, g * s.w + xv.w);
}

// ============================================================
extern "C" void kernel_launch(void* const* d_in, const int* in_sizes, int n_in,
                              void* d_out, int out_size)
{
    const float* x     = (const float*)d_in[0];
    const float* gamma = (const float*)d_in[1];
    const float* qw = (const float*)d_in[2];
    const float* qb = (const float*)d_in[3];
    const float* qs = (const float*)d_in[4];
    const float* qo = (const float*)d_in[5];
    const float* kw = (const float*)d_in[6];
    const float* kb = (const float*)d_in[7];
    const float* ks = (const float*)d_in[8];
    const float* ko = (const float*)d_in[9];
    const float* jw = (const float*)d_in[10];
    const float* jb = (const float*)d_in[11];
    const float* js = (const float*)d_in[12];
    const float* jo = (const float*)d_in[13];
    const float* vw = (const float*)d_in[14];
    const float* vb = (const float*)d_in[15];
    const float* vs = (const float*)d_in[16];
    const float* vo = (const float*)d_in[17];
    float* out = (float*)d_out;

    proj_kernel<<<dim3(16, 16, BATCH), 128>>>(x, qw, qb, qs, qo,
                                              kw, kb, ks, ko,
                                              jw, jb, js, jo,
                                              vw, vb, vs, vo);
    m_kernel<<<dim3(8, 8, BATCH), 256>>>();
    attn_kernel<<<dim3(MSPLIT, NSP / BLK_ROWS, BATCH), 128>>>();
    finish_kernel<<<(BATCH * NSP * NC) / 1024, 256>>>(x, gamma, out);
}